// round 14
// baseline (speedup 1.0000x reference)
#include <cuda_runtime.h>
#include <cuda_fp16.h>
#include <cstdint>

// SeqClassLSTM via mma.sync fp16 (sm_103-portable).
// R14: REGISTER-RESIDENT RECURRENCE. The m16n8k16 D-fragment ownership map
// equals the A-fragment map (rows r,r+8; col-pairs 2c,2c+1), so the epilogue's
// packed half2 h-outputs ARE the next step's A registers:
//   A0 = {q0pr0,q0pr1,q1pr0,q1pr1}, A1 = {q2pr0,q2pr1,q3pr0,q3pr1}.
// Deletes stmatrix/__syncwarp/ldmatrix and all h smem (the per-step critical
// path in R13). x k8-fragment rebuilt per step via 2 shuffles + ALU.
// Kept from R13: 32 seqs/warp (2 rb halves), single-fp16 W_hh, 0.5-prescaled
// i/f/o rows so MMA emits tanh's argument directly, tanh.approx.f16x2
// activations, fp32 cell state.

using u32 = uint32_t;

constexpr int T = 128;
constexpr int SEQ_CTA = 128;   // 32 per warp

__device__ __forceinline__ u32 sm_addr(const void* p) {
    u32 a;
    asm("{ .reg .u64 t; cvta.to.shared.u64 t, %1; cvt.u32.u64 %0, t; }" : "=r"(a) : "l"(p));
    return a;
}
// pack two f32 -> half2 (u32); LOW half = first arg
__device__ __forceinline__ u32 packh(float lo, float hi) {
    __half2 t = __floats2half2_rn(lo, hi);
    return *reinterpret_cast<u32*>(&t);
}
__device__ __forceinline__ __half2 asH2(u32 v) { return *reinterpret_cast<__half2*>(&v); }
__device__ __forceinline__ u32 asU(__half2 v) { return *reinterpret_cast<u32*>(&v); }
__device__ __forceinline__ __half2 tanh_h2(__half2 v) {
    u32 r, a = asU(v);
    asm("tanh.approx.f16x2 %0, %1;" : "=r"(r) : "r"(a));
    return asH2(r);
}
__device__ __forceinline__ void lds128(u32 r[4], u32 a) {
    asm volatile("ld.shared.v4.b32 {%0,%1,%2,%3}, [%4];"
                 : "=r"(r[0]), "=r"(r[1]), "=r"(r[2]), "=r"(r[3]) : "r"(a));
}
__device__ __forceinline__ u32 lds32(u32 a) {
    u32 r;
    asm volatile("ld.shared.u32 %0, [%1];" : "=r"(r) : "r"(a));
    return r;
}
__device__ __forceinline__ void mma16816(float d[4], const u32 a[4], u32 b0, u32 b1) {
    asm volatile("mma.sync.aligned.m16n8k16.row.col.f32.f16.f16.f32 "
                 "{%0,%1,%2,%3}, {%4,%5,%6,%7}, {%8,%9}, {%0,%1,%2,%3};"
                 : "+f"(d[0]), "+f"(d[1]), "+f"(d[2]), "+f"(d[3])
                 : "r"(a[0]), "r"(a[1]), "r"(a[2]), "r"(a[3]), "r"(b0), "r"(b1));
}
__device__ __forceinline__ void mma1688(float d[4], const u32 a[2], u32 b0) {
    asm volatile("mma.sync.aligned.m16n8k8.row.col.f32.f16.f16.f32 "
                 "{%0,%1,%2,%3}, {%4,%5}, {%6}, {%0,%1,%2,%3};"
                 : "+f"(d[0]), "+f"(d[1]), "+f"(d[2]), "+f"(d[3])
                 : "r"(a[0]), "r"(a[1]), "r"(b0));
}

__global__ void __launch_bounds__(128, 4)
lstm_hmma(const float* __restrict__ x,
          const float* __restrict__ W_ih,
          const float* __restrict__ W_hh,
          const float* __restrict__ b_ih,
          const float* __restrict__ b_hh,
          const float* __restrict__ W_fc,
          const float* __restrict__ b_fc,
          float* __restrict__ out,
          int B)
{
    // Btab[tau*32 + lane][4]: W fragments (i/f/o rows prescaled 0.5). 8KB.
    __shared__ u32 Btab[16 * 32 * 4];
    __shared__ u32 bxs[16 * 32];      // k8 bias/x B-frags, 2KB
    __shared__ float wfc_s[64];
    __shared__ float bfc_s[2];

    const int tid = threadIdx.x;
    const int wid = tid >> 5, lane = tid & 31;

    // ---- weight-fragment table; gate g (==2) unscaled, i/f/o scaled 0.5 ----
    for (int i = tid; i < 16 * 32 * 4; i += 128) {
        const int j   = i & 3;
        const int ln  = (i >> 2) & 31;
        const int tau = i >> 7;
        const int gate = tau >> 2;
        const float s = (gate == 2) ? 1.0f : 0.5f;
        const int n = tau * 8 + (ln >> 2);
        const int k = ((j >> 1) * 16) + ((j & 1) * 8) + 2 * (ln & 3);
        Btab[i] = packh(s * W_hh[n * 32 + k], s * W_hh[n * 32 + k + 1]);
    }
    // ---- k8 (bias/x) B fragments table (same 0.5 prescale on i/f/o) ----
    for (int i = tid; i < 16 * 32; i += 128) {
        const int ln = i & 31, tau = i >> 5;
        const int gate = tau >> 2;
        const float s = (gate == 2) ? 1.0f : 0.5f;
        const int sel = ln & 3;
        const int n = tau * 8 + (ln >> 2);
        const float bias = s * (b_ih[n] + b_hh[n]);
        const float wx = s * W_ih[n];
        const float bh = __half2float(__float2half_rn(bias));
        const float wh = __half2float(__float2half_rn(wx));
        u32 v;
        if (sel == 0)      v = packh(bh, bias - bh);      // k0=b_hi, k1=b_lo
        else if (sel == 1) v = packh(wh, wh);             // k2,k3 = wx_hi
        else if (sel == 2) v = packh(wx - wh, 0.0f);      // k4 = wx_lo
        else               v = 0u;
        bxs[i] = v;
    }
    if (tid < 64) wfc_s[tid] = W_fc[tid];
    if (tid < 2) bfc_s[tid] = b_fc[tid];
    __syncthreads();

    const u32 btb = sm_addr(Btab);
    const u32 bxb = sm_addr(bxs);
    const int cc = lane & 3;

    // each lane owns x of seq-in-warp = lane
    const int seqr = blockIdx.x * SEQ_CTA + wid * 32 + lane;
    const bool sv = (seqr < B);

    // h state: A fragments, register-resident. A0 = hid 0-15, A1 = hid 16-31.
    u32 A0[2][4], A1[2][4];
#pragma unroll
    for (int rb = 0; rb < 2; ++rb)
#pragma unroll
        for (int j = 0; j < 4; ++j) { A0[rb][j] = 0u; A1[rb][j] = 0u; }

    float cst[32];
#pragma unroll
    for (int i = 0; i < 32; ++i) cst[i] = 0.0f;

    const __half2 H05 = __floats2half2_rn(0.5f, 0.5f);
    const int srow = lane >> 2;   // fragment row r (0-7)

    float xcur = sv ? __ldg(&x[(size_t)seqr * T]) : 0.0f;

#pragma unroll 1
    for (int t = 0; t < T; ++t) {
        const float xnext = (sv && (t + 1) < T) ? __ldg(&x[(size_t)seqr * T + t + 1]) : 0.0f;

#pragma unroll
        for (int rb = 0; rb < 2; ++rb) {
            // ---- build x k8 A-fragment for rows (rb*16+srow, +8) ----
            const float xa = __shfl_sync(0xffffffffu, xcur, rb * 16 + srow);
            const float xbv = __shfl_sync(0xffffffffu, xcur, rb * 16 + srow + 8);
            u32 Ax[2];
            {
                const float xah = __half2float(__float2half_rn(xa));
                const float xbh = __half2float(__float2half_rn(xbv));
                if (cc == 0)      { Ax[0] = 0x3C003C00u;            Ax[1] = 0x3C003C00u; }
                else if (cc == 1) { Ax[0] = packh(xah, xa - xah);   Ax[1] = packh(xbh, xbv - xbh); }
                else if (cc == 2) { Ax[0] = packh(xah, 0.0f);       Ax[1] = packh(xbh, 0.0f); }
                else              { Ax[0] = 0u;                     Ax[1] = 0u; }
            }

            u32 n0[4], n1[4];
#pragma unroll
            for (int q = 0; q < 4; ++q) {
                float dd[4][4];
#pragma unroll
                for (int gate = 0; gate < 4; ++gate) {
                    const int tau = q + gate * 4;
                    u32 bh[4];
                    lds128(bh, btb + (u32)(tau * 32 + lane) * 16u);
                    const u32 bxv = lds32(bxb + (u32)(tau * 32 + lane) * 4u);
                    float* d = dd[gate];
                    d[0] = 0.0f; d[1] = 0.0f; d[2] = 0.0f; d[3] = 0.0f;
                    mma16816(d, A0[rb], bh[0], bh[1]);
                    mma16816(d, A1[rb], bh[2], bh[3]);
                    mma1688(d, Ax, bxv);
                }
#pragma unroll
                for (int pr = 0; pr < 2; ++pr) {
                    const int e = 2 * pr;
                    const __half2 iv = asH2(packh(dd[0][e], dd[0][e + 1]));
                    const __half2 fv = asH2(packh(dd[1][e], dd[1][e + 1]));
                    const __half2 gv = asH2(packh(dd[2][e], dd[2][e + 1]));
                    const __half2 ov = asH2(packh(dd[3][e], dd[3][e + 1]));
                    const __half2 si = __hfma2(tanh_h2(iv), H05, H05);
                    const __half2 sf = __hfma2(tanh_h2(fv), H05, H05);
                    const __half2 tg = tanh_h2(gv);
                    const __half2 so = __hfma2(tanh_h2(ov), H05, H05);
                    const __half2 p = __hmul2(si, tg);
                    const int ci = (rb * 2 + pr) * 8 + q * 2;
                    const float cn0 = fmaf(__low2float(sf),  cst[ci],     __low2float(p));
                    const float cn1 = fmaf(__high2float(sf), cst[ci + 1], __high2float(p));
                    cst[ci] = cn0;
                    cst[ci + 1] = cn1;
                    const __half2 tc = tanh_h2(asH2(packh(cn0, cn1)));
                    const u32 hv = asU(__hmul2(so, tc));
                    // D-frag == A-frag identity: route into next step's A regs
                    if (q == 0)      n0[pr]     = hv;
                    else if (q == 1) n0[2 + pr] = hv;
                    else if (q == 2) n1[pr]     = hv;
                    else             n1[2 + pr] = hv;
                }
            }
#pragma unroll
            for (int j = 0; j < 4; ++j) { A0[rb][j] = n0[j]; A1[rb][j] = n1[j]; }
        }
        xcur = xnext;
    }

    // ---- FC directly from h registers ----
#pragma unroll
    for (int rb = 0; rb < 2; ++rb) {
        float acc[2][2] = {{0.0f, 0.0f}, {0.0f, 0.0f}};
#pragma unroll
        for (int part = 0; part < 2; ++part) {
#pragma unroll
            for (int j = 0; j < 4; ++j) {
                const u32 v = part ? A1[rb][j] : A0[rb][j];
                const int rg = j & 1;                       // 0: rows r, 1: rows r+8
                const int hid = part * 16 + (j >> 1) * 8 + 2 * cc;
                const __half2 hh = asH2(v);
                const float h0 = __low2float(hh);
                const float h1 = __high2float(hh);
                acc[rg][0] = fmaf(h0, wfc_s[hid],      fmaf(h1, wfc_s[hid + 1],      acc[rg][0]));
                acc[rg][1] = fmaf(h0, wfc_s[32 + hid], fmaf(h1, wfc_s[32 + hid + 1], acc[rg][1]));
            }
        }
#pragma unroll
        for (int rg = 0; rg < 2; ++rg)
#pragma unroll
            for (int o = 0; o < 2; ++o) {
                acc[rg][o] += __shfl_xor_sync(0xffffffffu, acc[rg][o], 1);
                acc[rg][o] += __shfl_xor_sync(0xffffffffu, acc[rg][o], 2);
            }
        if (cc == 0) {
            const int s0 = blockIdx.x * SEQ_CTA + wid * 32 + rb * 16 + srow;
            if (s0 < B) {
                out[(size_t)s0 * 2 + 0] = acc[0][0] + bfc_s[0];
                out[(size_t)s0 * 2 + 1] = acc[0][1] + bfc_s[1];
            }
            const int s1 = s0 + 8;
            if (s1 < B) {
                out[(size_t)s1 * 2 + 0] = acc[1][0] + bfc_s[0];
                out[(size_t)s1 * 2 + 1] = acc[1][1] + bfc_s[1];
            }
        }
    }
}

extern "C" void kernel_launch(void* const* d_in, const int* in_sizes, int n_in,
                              void* d_out, int out_size)
{
    const float* x    = (const float*)d_in[0];
    const float* W_ih = (const float*)d_in[1];
    const float* W_hh = (const float*)d_in[2];
    const float* b_ih = (const float*)d_in[3];
    const float* b_hh = (const float*)d_in[4];
    const float* W_fc = (const float*)d_in[5];
    const float* b_fc = (const float*)d_in[6];
    float* out = (float*)d_out;

    const int B = in_sizes[0] / T;                // x has B*T elements
    const int blocks = (B + SEQ_CTA - 1) / SEQ_CTA;

    lstm_hmma<<<blocks, 128>>>(x, W_ih, W_hh, b_ih, b_hh, W_fc, b_fc, out, B);
}

// round 15
// speedup vs baseline: 1.0618x; 1.0618x over previous
#include <cuda_runtime.h>
#include <cuda_fp16.h>
#include <cstdint>

// SeqClassLSTM via mma.sync fp16 (sm_103-portable).
// R15: R14's register-resident recurrence (D-fragment map == A-fragment map,
// so epilogue half2 outputs ARE the next step's A registers; no h smem, no
// stmatrix/ldmatrix/syncwarp) — but at occupancy 3 (168-reg budget).
// R14's launch_bounds(128,4) capped regs at 128 and SPILLED the state to
// local (L2 0.9%->21.6%, alu +8pts) -> regression. Also hoists the
// time-invariant k8 bias/x B-fragments into registers (bx[16]).
// Kept: 32 seqs/warp (2 rb halves), single-fp16 W_hh, 0.5-prescaled i/f/o
// rows (MMA emits tanh's argument), tanh.approx.f16x2, fp32 cell state.

using u32 = uint32_t;

constexpr int T = 128;
constexpr int SEQ_CTA = 128;   // 32 per warp

__device__ __forceinline__ u32 sm_addr(const void* p) {
    u32 a;
    asm("{ .reg .u64 t; cvta.to.shared.u64 t, %1; cvt.u32.u64 %0, t; }" : "=r"(a) : "l"(p));
    return a;
}
// pack two f32 -> half2 (u32); LOW half = first arg
__device__ __forceinline__ u32 packh(float lo, float hi) {
    __half2 t = __floats2half2_rn(lo, hi);
    return *reinterpret_cast<u32*>(&t);
}
__device__ __forceinline__ __half2 asH2(u32 v) { return *reinterpret_cast<__half2*>(&v); }
__device__ __forceinline__ u32 asU(__half2 v) { return *reinterpret_cast<u32*>(&v); }
__device__ __forceinline__ __half2 tanh_h2(__half2 v) {
    u32 r, a = asU(v);
    asm("tanh.approx.f16x2 %0, %1;" : "=r"(r) : "r"(a));
    return asH2(r);
}
__device__ __forceinline__ void lds128(u32 r[4], u32 a) {
    asm volatile("ld.shared.v4.b32 {%0,%1,%2,%3}, [%4];"
                 : "=r"(r[0]), "=r"(r[1]), "=r"(r[2]), "=r"(r[3]) : "r"(a));
}
__device__ __forceinline__ void mma16816(float d[4], const u32 a[4], u32 b0, u32 b1) {
    asm volatile("mma.sync.aligned.m16n8k16.row.col.f32.f16.f16.f32 "
                 "{%0,%1,%2,%3}, {%4,%5,%6,%7}, {%8,%9}, {%0,%1,%2,%3};"
                 : "+f"(d[0]), "+f"(d[1]), "+f"(d[2]), "+f"(d[3])
                 : "r"(a[0]), "r"(a[1]), "r"(a[2]), "r"(a[3]), "r"(b0), "r"(b1));
}
__device__ __forceinline__ void mma1688(float d[4], const u32 a[2], u32 b0) {
    asm volatile("mma.sync.aligned.m16n8k8.row.col.f32.f16.f16.f32 "
                 "{%0,%1,%2,%3}, {%4,%5}, {%6}, {%0,%1,%2,%3};"
                 : "+f"(d[0]), "+f"(d[1]), "+f"(d[2]), "+f"(d[3])
                 : "r"(a[0]), "r"(a[1]), "r"(b0));
}

__global__ void __launch_bounds__(128, 3)
lstm_hmma(const float* __restrict__ x,
          const float* __restrict__ W_ih,
          const float* __restrict__ W_hh,
          const float* __restrict__ b_ih,
          const float* __restrict__ b_hh,
          const float* __restrict__ W_fc,
          const float* __restrict__ b_fc,
          float* __restrict__ out,
          int B)
{
    // Btab[tau*32 + lane][4]: W fragments (i/f/o rows prescaled 0.5). 8KB.
    __shared__ u32 Btab[16 * 32 * 4];
    __shared__ float wfc_s[64];
    __shared__ float bfc_s[2];

    const int tid = threadIdx.x;
    const int wid = tid >> 5, lane = tid & 31;

    // ---- weight-fragment table; gate g (==2) unscaled, i/f/o scaled 0.5 ----
    for (int i = tid; i < 16 * 32 * 4; i += 128) {
        const int j   = i & 3;
        const int ln  = (i >> 2) & 31;
        const int tau = i >> 7;
        const int gate = tau >> 2;
        const float s = (gate == 2) ? 1.0f : 0.5f;
        const int n = tau * 8 + (ln >> 2);
        const int k = ((j >> 1) * 16) + ((j & 1) * 8) + 2 * (ln & 3);
        Btab[i] = packh(s * W_hh[n * 32 + k], s * W_hh[n * 32 + k + 1]);
    }
    if (tid < 64) wfc_s[tid] = W_fc[tid];
    if (tid < 2) bfc_s[tid] = b_fc[tid];

    // ---- k8 (bias/x) B fragments: time-invariant -> registers ----
    u32 bx[16];
    {
        const int sel = lane & 3;
#pragma unroll
        for (int tau = 0; tau < 16; ++tau) {
            const int gate = tau >> 2;
            const float s = (gate == 2) ? 1.0f : 0.5f;
            const int n = tau * 8 + (lane >> 2);
            const float bias = s * (b_ih[n] + b_hh[n]);
            const float wx = s * W_ih[n];
            const float bh = __half2float(__float2half_rn(bias));
            const float wh = __half2float(__float2half_rn(wx));
            u32 v;
            if (sel == 0)      v = packh(bh, bias - bh);      // k0=b_hi, k1=b_lo
            else if (sel == 1) v = packh(wh, wh);             // k2,k3 = wx_hi
            else if (sel == 2) v = packh(wx - wh, 0.0f);      // k4 = wx_lo
            else               v = 0u;
            bx[tau] = v;
        }
    }
    __syncthreads();

    const u32 btb = sm_addr(Btab);
    const int cc = lane & 3;

    // each lane owns x of seq-in-warp = lane
    const int seqr = blockIdx.x * SEQ_CTA + wid * 32 + lane;
    const bool sv = (seqr < B);

    // h state: A fragments, register-resident. A0 = hid 0-15, A1 = hid 16-31.
    u32 A0[2][4], A1[2][4];
#pragma unroll
    for (int rb = 0; rb < 2; ++rb)
#pragma unroll
        for (int j = 0; j < 4; ++j) { A0[rb][j] = 0u; A1[rb][j] = 0u; }

    float cst[32];
#pragma unroll
    for (int i = 0; i < 32; ++i) cst[i] = 0.0f;

    const __half2 H05 = __floats2half2_rn(0.5f, 0.5f);
    const int srow = lane >> 2;   // fragment row r (0-7)

    float xcur = sv ? __ldg(&x[(size_t)seqr * T]) : 0.0f;

#pragma unroll 1
    for (int t = 0; t < T; ++t) {
        const float xnext = (sv && (t + 1) < T) ? __ldg(&x[(size_t)seqr * T + t + 1]) : 0.0f;

#pragma unroll
        for (int rb = 0; rb < 2; ++rb) {
            // ---- build x k8 A-fragment for rows (rb*16+srow, +8) ----
            const float xa = __shfl_sync(0xffffffffu, xcur, rb * 16 + srow);
            const float xbv = __shfl_sync(0xffffffffu, xcur, rb * 16 + srow + 8);
            u32 Ax[2];
            {
                const float xah = __half2float(__float2half_rn(xa));
                const float xbh = __half2float(__float2half_rn(xbv));
                if (cc == 0)      { Ax[0] = 0x3C003C00u;            Ax[1] = 0x3C003C00u; }
                else if (cc == 1) { Ax[0] = packh(xah, xa - xah);   Ax[1] = packh(xbh, xbv - xbh); }
                else if (cc == 2) { Ax[0] = packh(xah, 0.0f);       Ax[1] = packh(xbh, 0.0f); }
                else              { Ax[0] = 0u;                     Ax[1] = 0u; }
            }

            u32 n0[4], n1[4];
#pragma unroll
            for (int q = 0; q < 4; ++q) {
                float dd[4][4];
#pragma unroll
                for (int gate = 0; gate < 4; ++gate) {
                    const int tau = q + gate * 4;
                    u32 bh[4];
                    lds128(bh, btb + (u32)(tau * 32 + lane) * 16u);
                    float* d = dd[gate];
                    d[0] = 0.0f; d[1] = 0.0f; d[2] = 0.0f; d[3] = 0.0f;
                    mma16816(d, A0[rb], bh[0], bh[1]);
                    mma16816(d, A1[rb], bh[2], bh[3]);
                    mma1688(d, Ax, bx[tau]);
                }
#pragma unroll
                for (int pr = 0; pr < 2; ++pr) {
                    const int e = 2 * pr;
                    const __half2 iv = asH2(packh(dd[0][e], dd[0][e + 1]));
                    const __half2 fv = asH2(packh(dd[1][e], dd[1][e + 1]));
                    const __half2 gv = asH2(packh(dd[2][e], dd[2][e + 1]));
                    const __half2 ov = asH2(packh(dd[3][e], dd[3][e + 1]));
                    const __half2 si = __hfma2(tanh_h2(iv), H05, H05);
                    const __half2 sf = __hfma2(tanh_h2(fv), H05, H05);
                    const __half2 tg = tanh_h2(gv);
                    const __half2 so = __hfma2(tanh_h2(ov), H05, H05);
                    const __half2 p = __hmul2(si, tg);
                    const int ci = (rb * 2 + pr) * 8 + q * 2;
                    const float cn0 = fmaf(__low2float(sf),  cst[ci],     __low2float(p));
                    const float cn1 = fmaf(__high2float(sf), cst[ci + 1], __high2float(p));
                    cst[ci] = cn0;
                    cst[ci + 1] = cn1;
                    const __half2 tc = tanh_h2(asH2(packh(cn0, cn1)));
                    const u32 hv = asU(__hmul2(so, tc));
                    // D-frag == A-frag identity: route into next step's A regs
                    if (q == 0)      n0[pr]     = hv;
                    else if (q == 1) n0[2 + pr] = hv;
                    else if (q == 2) n1[pr]     = hv;
                    else             n1[2 + pr] = hv;
                }
            }
#pragma unroll
            for (int j = 0; j < 4; ++j) { A0[rb][j] = n0[j]; A1[rb][j] = n1[j]; }
        }
        xcur = xnext;
    }

    // ---- FC directly from h registers ----
#pragma unroll
    for (int rb = 0; rb < 2; ++rb) {
        float acc[2][2] = {{0.0f, 0.0f}, {0.0f, 0.0f}};
#pragma unroll
        for (int part = 0; part < 2; ++part) {
#pragma unroll
            for (int j = 0; j < 4; ++j) {
                const u32 v = part ? A1[rb][j] : A0[rb][j];
                const int rg = j & 1;                       // 0: rows r, 1: rows r+8
                const int hid = part * 16 + (j >> 1) * 8 + 2 * cc;
                const __half2 hh = asH2(v);
                const float h0 = __low2float(hh);
                const float h1 = __high2float(hh);
                acc[rg][0] = fmaf(h0, wfc_s[hid],      fmaf(h1, wfc_s[hid + 1],      acc[rg][0]));
                acc[rg][1] = fmaf(h0, wfc_s[32 + hid], fmaf(h1, wfc_s[32 + hid + 1], acc[rg][1]));
            }
        }
#pragma unroll
        for (int rg = 0; rg < 2; ++rg)
#pragma unroll
            for (int o = 0; o < 2; ++o) {
                acc[rg][o] += __shfl_xor_sync(0xffffffffu, acc[rg][o], 1);
                acc[rg][o] += __shfl_xor_sync(0xffffffffu, acc[rg][o], 2);
            }
        if (cc == 0) {
            const int s0 = blockIdx.x * SEQ_CTA + wid * 32 + rb * 16 + srow;
            if (s0 < B) {
                out[(size_t)s0 * 2 + 0] = acc[0][0] + bfc_s[0];
                out[(size_t)s0 * 2 + 1] = acc[0][1] + bfc_s[1];
            }
            const int s1 = s0 + 8;
            if (s1 < B) {
                out[(size_t)s1 * 2 + 0] = acc[1][0] + bfc_s[0];
                out[(size_t)s1 * 2 + 1] = acc[1][1] + bfc_s[1];
            }
        }
    }
}

extern "C" void kernel_launch(void* const* d_in, const int* in_sizes, int n_in,
                              void* d_out, int out_size)
{
    const float* x    = (const float*)d_in[0];
    const float* W_ih = (const float*)d_in[1];
    const float* W_hh = (const float*)d_in[2];
    const float* b_ih = (const float*)d_in[3];
    const float* b_hh = (const float*)d_in[4];
    const float* W_fc = (const float*)d_in[5];
    const float* b_fc = (const float*)d_in[6];
    float* out = (float*)d_out;

    const int B = in_sizes[0] / T;                // x has B*T elements
    const int blocks = (B + SEQ_CTA - 1) / SEQ_CTA;

    lstm_hmma<<<blocks, 128>>>(x, W_ih, W_hh, b_ih, b_hh, W_fc, b_fc, out, B);
}